// round 6
// baseline (speedup 1.0000x reference)
#include <cuda_runtime.h>
#include <stdint.h>

#define DIM_IN 16
#define CH 128
#define DIM_OUT 99
#define MAX_NNZ 512
#define EPB 2                    // edges per block = warps per block
#define THREADS (EPB * 32)

// 8-byte term, one LDS.64 broadcast:
//   .x = ox | (oy << 16)  u16 byte offsets into the 8 KB row block (<= 7680)
//   .y = cg bits
__device__ uint2 g_terms[MAX_NNZ];
__device__ int   g_rowptr[DIM_OUT + 1];

// ---------------------------------------------------------------------------
// Prep: deterministic stable counting sort of terms by mu3 into CSR layout.
// ---------------------------------------------------------------------------
__global__ void prep_kernel(const int* __restrict__ mu1,
                            const int* __restrict__ mu2,
                            const int* __restrict__ mu3,
                            const float* __restrict__ cg,
                            int nnz)
{
    __shared__ int sm3[MAX_NNZ];
    __shared__ int hist[DIM_OUT + 1];
    int t = threadIdx.x;

    if (t < DIM_OUT + 1) hist[t] = 0;
    __syncthreads();

    for (int k = t; k < nnz; k += blockDim.x) {
        int m = mu3[k];
        sm3[k] = m;
        atomicAdd(&hist[m], 1);
    }
    __syncthreads();

    if (t == 0) {
        int s = 0;
        for (int o = 0; o < DIM_OUT; o++) {
            int h = hist[o];
            g_rowptr[o] = s;
            hist[o] = s;       // running row start
            s += h;
        }
        g_rowptr[DIM_OUT] = s;
    }
    __syncthreads();

    // stable scatter: rank = #earlier terms with same mu3 (deterministic)
    for (int k = t; k < nnz; k += blockDim.x) {
        int m = sm3[k];
        int rank = 0;
        for (int j = 0; j < k; j++) rank += (sm3[j] == m);
        int pos = hist[m] + rank;
        unsigned int ox = (unsigned int)mu1[k] * (CH * 4u);
        unsigned int oy = (unsigned int)mu2[k] * (CH * 4u);
        uint2 tm;
        tm.x = ox | (oy << 16);
        tm.y = __float_as_uint(cg[k]);
        g_terms[pos] = tm;
    }
}

// ---------------------------------------------------------------------------
// Main: one WARP per edge (EPB warps per block). Each lane owns 4 consecutive
// channels (16 B) processed with two packed f32x2 ops. x/y rows fetched with
// LDS.128 (conflict-free, 512 B/warp). Terms in shared, LDS.64 broadcast.
// Each output element written exactly once, STG.128.
// ---------------------------------------------------------------------------
__global__ __launch_bounds__(THREADS, 6)
void tp_kernel(const float* __restrict__ x,
               const float* __restrict__ y,
               float* __restrict__ out)
{
    __shared__ __align__(16) float sx[EPB][DIM_IN * CH];   // 8 KB per edge
    __shared__ __align__(16) float sy[EPB][DIM_IN * CH];   // 8 KB per edge
    __shared__ __align__(16) uint2 sterms[MAX_NNZ];        // 4 KB
    __shared__ int srp[DIM_OUT + 1];

    const int t    = threadIdx.x;
    const int w    = t >> 5;             // warp = edge slot
    const int lane = t & 31;
    const long long edge = (long long)blockIdx.x * EPB + w;

    // cooperative (block-wide) load of terms + rowptr, once
#pragma unroll
    for (int i = 0; i < MAX_NNZ / THREADS; i++)
        sterms[t + i * THREADS] = g_terms[t + i * THREADS];
    for (int i = t; i < DIM_OUT + 1; i += THREADS)
        srp[i] = g_rowptr[i];
    __syncthreads();

    // per-warp tile load: 2048 floats = 512 float4 each; 16 per lane
    const float4* x4 = (const float4*)(x + edge * (DIM_IN * CH));
    const float4* y4 = (const float4*)(y + edge * (DIM_IN * CH));
    float4* sx4 = (float4*)sx[w];
    float4* sy4 = (float4*)sy[w];
#pragma unroll
    for (int i = 0; i < (DIM_IN * CH / 4) / 32; i++) {
        sx4[lane + i * 32] = x4[lane + i * 32];
        sy4[lane + i * 32] = y4[lane + i * 32];
    }
    __syncwarp();

    const char* sxb = (const char*)sx[w] + lane * 16;   // 4-channel slice
    const char* syb = (const char*)sy[w] + lane * 16;
    float* oute = out + edge * (DIM_OUT * CH) + lane * 4;

    int k0 = srp[0];
#pragma unroll 1
    for (int o = 0; o < DIM_OUT; o++) {
        const int k1 = srp[o + 1];
        unsigned long long a01 = 0ull, a23 = 0ull;   // {+0,+0} packed f32x2
#pragma unroll 4
        for (int k = k0; k < k1; ++k) {
            uint2 tm = sterms[k];
            unsigned int ox = tm.x & 0xFFFFu;
            unsigned int oy = tm.x >> 16;
            unsigned long long cgp;
            asm("mov.b64 %0, {%1, %1};" : "=l"(cgp) : "r"(tm.y));
            ulonglong2 xv = *(const ulonglong2*)(sxb + ox);   // LDS.128
            ulonglong2 yv = *(const ulonglong2*)(syb + oy);   // LDS.128
            unsigned long long p01, p23;
            asm("mul.rn.f32x2 %0, %1, %2;" : "=l"(p01) : "l"(xv.x), "l"(yv.x));
            asm("mul.rn.f32x2 %0, %1, %2;" : "=l"(p23) : "l"(xv.y), "l"(yv.y));
            asm("fma.rn.f32x2 %0, %1, %2, %3;"
                : "=l"(a01) : "l"(p01), "l"(cgp), "l"(a01));
            asm("fma.rn.f32x2 %0, %1, %2, %3;"
                : "=l"(a23) : "l"(p23), "l"(cgp), "l"(a23));
        }
        ulonglong2 st;
        st.x = a01;
        st.y = a23;
        *(ulonglong2*)oute = st;    // STG.128
        oute += CH;
        k0 = k1;
    }
}

// ---------------------------------------------------------------------------
// Inputs (metadata order): x f32 [N,16,128], y f32 [N,16,128],
//                          mu1 i32 [nnz], mu2 i32 [nnz], mu3 i32 [nnz], cg f32 [nnz]
// Output: f32 [N,99,128]
// ---------------------------------------------------------------------------
extern "C" void kernel_launch(void* const* d_in, const int* in_sizes, int n_in,
                              void* d_out, int out_size)
{
    const float* x   = (const float*)d_in[0];
    const float* y   = (const float*)d_in[1];
    const int*   mu1 = (const int*)d_in[2];
    const int*   mu2 = (const int*)d_in[3];
    const int*   mu3 = (const int*)d_in[4];
    const float* cg  = (const float*)d_in[5];

    int nnz = in_sizes[2];
    if (nnz > MAX_NNZ) nnz = MAX_NNZ;   // capacity guard (actual nnz ~350)
    int N = in_sizes[0] / (DIM_IN * CH);
    int nBlocks = (N + EPB - 1) / EPB;

    prep_kernel<<<1, 1024>>>(mu1, mu2, mu3, cg, nnz);
    tp_kernel<<<nBlocks, THREADS>>>(x, y, (float*)d_out);
}

// round 7
// speedup vs baseline: 1.0678x; 1.0678x over previous
#include <cuda_runtime.h>
#include <stdint.h>

#define DIM_IN 16
#define CH 128
#define DIM_OUT 99
#define MAX_NNZ 512
#define EPB 2              // edges per block
#define THREADS (EPB * 64)

// 8-byte term:
//   .x = ox | (oy << 16)  u16 byte offsets into the 8 KB row block (<= 7680)
//   .y = cg bits
__device__ uint2 g_terms[MAX_NNZ];
__device__ int   g_rowptr[DIM_OUT + 1];

// Constant-memory copies (filled by D2D memcpy inside the graph). Term fetch
// in the hot loop becomes LDC (constant port) instead of LDS (L1 crossbar).
__constant__ uint2 c_terms[MAX_NNZ];
__constant__ int   c_rowptr[DIM_OUT + 1];

// ---------------------------------------------------------------------------
// Prep: deterministic stable counting sort of terms by mu3 into CSR layout.
// ---------------------------------------------------------------------------
__global__ void prep_kernel(const int* __restrict__ mu1,
                            const int* __restrict__ mu2,
                            const int* __restrict__ mu3,
                            const float* __restrict__ cg,
                            int nnz)
{
    __shared__ int sm3[MAX_NNZ];
    __shared__ int hist[DIM_OUT + 1];
    int t = threadIdx.x;

    if (t < DIM_OUT + 1) hist[t] = 0;
    __syncthreads();

    for (int k = t; k < nnz; k += blockDim.x) {
        int m = mu3[k];
        sm3[k] = m;
        atomicAdd(&hist[m], 1);
    }
    __syncthreads();

    if (t == 0) {
        int s = 0;
        for (int o = 0; o < DIM_OUT; o++) {
            int h = hist[o];
            g_rowptr[o] = s;
            hist[o] = s;       // running row start
            s += h;
        }
        g_rowptr[DIM_OUT] = s;
    }
    __syncthreads();

    // stable scatter: rank = #earlier terms with same mu3 (deterministic)
    for (int k = t; k < nnz; k += blockDim.x) {
        int m = sm3[k];
        int rank = 0;
        for (int j = 0; j < k; j++) rank += (sm3[j] == m);
        int pos = hist[m] + rank;
        unsigned int ox = (unsigned int)mu1[k] * (CH * 4u);
        unsigned int oy = (unsigned int)mu2[k] * (CH * 4u);
        uint2 tm;
        tm.x = ox | (oy << 16);
        tm.y = __float_as_uint(cg[k]);
        g_terms[pos] = tm;
    }
}

// ---------------------------------------------------------------------------
// Main: 2 edges per 128-thread block; 64 threads per edge, one channel pair
// per thread, packed f32x2 math. Terms come from constant memory (LDC
// broadcast — zero L1TEX wavefronts). Each output element written once.
// ---------------------------------------------------------------------------
__global__ __launch_bounds__(THREADS, 6)
void tp_kernel(const float* __restrict__ x,
               const float* __restrict__ y,
               float* __restrict__ out)
{
    __shared__ __align__(16) float sx[EPB * DIM_IN * CH];   // 16 KB
    __shared__ __align__(16) float sy[EPB * DIM_IN * CH];   // 16 KB

    const int t    = threadIdx.x;        // 0..127
    const int sub  = t >> 6;             // edge within block
    const int lane = t & 63;             // channel pair within edge
    const long long ebase = (long long)blockIdx.x * EPB;

    // cooperative load of both edges' x/y tiles (contiguous in gmem)
    const float4* x4 = (const float4*)(x + ebase * (DIM_IN * CH));
    const float4* y4 = (const float4*)(y + ebase * (DIM_IN * CH));
#pragma unroll
    for (int i = 0; i < (EPB * DIM_IN * CH / 4) / THREADS; i++) {
        ((float4*)sx)[t + i * THREADS] = x4[t + i * THREADS];
        ((float4*)sy)[t + i * THREADS] = y4[t + i * THREADS];
    }
    __syncthreads();

    const char* sxb = (const char*)(sx + sub * (DIM_IN * CH)) + lane * 8;
    const char* syb = (const char*)(sy + sub * (DIM_IN * CH)) + lane * 8;
    float* oute = out + (ebase + sub) * (DIM_OUT * CH) + lane * 2;

    int k0 = c_rowptr[0];
#pragma unroll 1
    for (int o = 0; o < DIM_OUT; o++) {
        const int k1 = c_rowptr[o + 1];
        unsigned long long acc = 0ull;   // {+0.0f, +0.0f}
#pragma unroll 4
        for (int k = k0; k < k1; ++k) {
            uint2 tm = c_terms[k];                 // LDC.64 broadcast
            unsigned int ox = tm.x & 0xFFFFu;
            unsigned int oy = tm.x >> 16;
            unsigned long long cgp;
            asm("mov.b64 %0, {%1, %1};" : "=l"(cgp) : "r"(tm.y));
            unsigned long long xv = *(const unsigned long long*)(sxb + ox);
            unsigned long long yv = *(const unsigned long long*)(syb + oy);
            unsigned long long p;
            asm("mul.rn.f32x2 %0, %1, %2;" : "=l"(p) : "l"(xv), "l"(yv));
            asm("fma.rn.f32x2 %0, %1, %2, %3;"
                : "=l"(acc) : "l"(p), "l"(cgp), "l"(acc));
        }
        *(unsigned long long*)(oute) = acc;
        oute += CH;
        k0 = k1;
    }
}

// ---------------------------------------------------------------------------
// Inputs (metadata order): x f32 [N,16,128], y f32 [N,16,128],
//                          mu1 i32 [nnz], mu2 i32 [nnz], mu3 i32 [nnz], cg f32 [nnz]
// Output: f32 [N,99,128]
// ---------------------------------------------------------------------------
extern "C" void kernel_launch(void* const* d_in, const int* in_sizes, int n_in,
                              void* d_out, int out_size)
{
    const float* x   = (const float*)d_in[0];
    const float* y   = (const float*)d_in[1];
    const int*   mu1 = (const int*)d_in[2];
    const int*   mu2 = (const int*)d_in[3];
    const int*   mu3 = (const int*)d_in[4];
    const float* cg  = (const float*)d_in[5];

    int nnz = in_sizes[2];
    if (nnz > MAX_NNZ) nnz = MAX_NNZ;   // capacity guard (actual nnz ~350)
    int N = in_sizes[0] / (DIM_IN * CH);
    int nBlocks = (N + EPB - 1) / EPB;

    prep_kernel<<<1, 1024>>>(mu1, mu2, mu3, cg, nnz);

    // Device->device copies of the prepared tables into constant memory.
    // These become memcpy nodes in the captured graph (D2D is allowed).
    void* gt_addr = nullptr;
    void* gr_addr = nullptr;
    cudaGetSymbolAddress(&gt_addr, g_terms);
    cudaGetSymbolAddress(&gr_addr, g_rowptr);
    cudaMemcpyToSymbolAsync(c_terms, gt_addr, sizeof(uint2) * MAX_NNZ, 0,
                            cudaMemcpyDeviceToDevice, 0);
    cudaMemcpyToSymbolAsync(c_rowptr, gr_addr, sizeof(int) * (DIM_OUT + 1), 0,
                            cudaMemcpyDeviceToDevice, 0);

    tp_kernel<<<nBlocks, THREADS>>>(x, y, (float*)d_out);
}